// round 5
// baseline (speedup 1.0000x reference)
#include <cuda_runtime.h>

// v: [8][1024][8][64] f32, w: [1][8][63] f32, out: [8][1024][8][64] f32
// Factorization (s=32, j = a*32+b, l = c*32+e):
//   out[n,j,h,d] = A[n,h,a,d] + B[n,h,b,d]
//   A = bias @ R,  B = bias @ C
//   R[c,d] = sum_e v[n, c*32+e, h, d],  C[e,d] = sum_c v[n, c*32+e, h, d]
//   bias[h,j,k] = w[h, (32 - k + j) mod 63]
//
// SINGLE fused kernel: block = (n, h, d-quarter). 256 blocks x 512 threads,
// 2 blocks/SM (launch_bounds caps regs). Each block reads its 64KB v slice,
// builds R,C,A,B in smem, writes its 64KB out slice.

__global__ __launch_bounds__(512, 2)
void fused_kernel(const float4* __restrict__ v4,
                  const float*  __restrict__ w,
                  float4* __restrict__ out4) {
    int blk = blockIdx.x;
    int q = blk & 3;               // d-quarter: float4 cols [q*4, q*4+4)
    int h = (blk >> 2) & 7;
    int n = blk >> 5;
    int tid = threadIdx.x;

    __shared__ float4 sRp[4][32][4];   // pass-1 partials (eh split)
    __shared__ float4 sCp[4][32][4];   // pass-2 partials
    __shared__ float4 sR[32][4], sC[32][4];
    __shared__ float4 sA[32][4], sB[32][4];
    __shared__ float  sb[32][33];      // bias[j][k], padded

    int c  = tid >> 4;        // 0..31  (c for pass1, e for pass2)
    int eh = (tid >> 2) & 3;  // 0..3   row sub-group
    int d4 = tid & 3;         // 0..3   float4 col within quarter

    const float4* base = v4 + ((size_t)n * 1024) * 128 + h * 16 + q * 4 + d4;

    // ---- Pass 1: R partials. rows l = c*32 + eh*8 + i (contiguous) ----
    {
        const float4* pv = base + (size_t)(c * 32 + eh * 8) * 128;
        float4 acc = make_float4(0.f, 0.f, 0.f, 0.f);
        #pragma unroll
        for (int i = 0; i < 8; ++i) {
            float4 x = pv[i * 128];
            acc.x += x.x; acc.y += x.y; acc.z += x.z; acc.w += x.w;
        }
        sRp[eh][c][d4] = acc;
    }

    // ---- Pass 2: C partials. rows l = (eh*8+i)*32 + c (L1/L2 re-hit) ----
    {
        const float4* pv = base + (size_t)(eh * 8 * 32 + c) * 128;
        float4 acc = make_float4(0.f, 0.f, 0.f, 0.f);
        #pragma unroll
        for (int i = 0; i < 8; ++i) {
            float4 x = pv[i * 32 * 128];
            acc.x += x.x; acc.y += x.y; acc.z += x.z; acc.w += x.w;
        }
        sCp[eh][c][d4] = acc;
    }

    // ---- bias tile (2 entries/thread) ----
    for (int idx = tid; idx < 1024; idx += 512) {
        int j = idx >> 5, k = idx & 31;
        sb[j][k] = w[h * 63 + ((32 - k + j) % 63)];
    }
    __syncthreads();

    // ---- combine partials (256 threads: 128 for R, 128 for C) ----
    if (tid < 256) {
        int t  = tid & 127;
        int kk = t >> 2, dd = t & 3;
        if (tid < 128) {
            float4 a = sRp[0][kk][dd], b = sRp[1][kk][dd];
            float4 cc = sRp[2][kk][dd], e = sRp[3][kk][dd];
            a.x = (a.x + b.x) + (cc.x + e.x);
            a.y = (a.y + b.y) + (cc.y + e.y);
            a.z = (a.z + b.z) + (cc.z + e.z);
            a.w = (a.w + b.w) + (cc.w + e.w);
            sR[kk][dd] = a;
        } else {
            float4 a = sCp[0][kk][dd], b = sCp[1][kk][dd];
            float4 cc = sCp[2][kk][dd], e = sCp[3][kk][dd];
            a.x = (a.x + b.x) + (cc.x + e.x);
            a.y = (a.y + b.y) + (cc.y + e.y);
            a.z = (a.z + b.z) + (cc.z + e.z);
            a.w = (a.w + b.w) + (cc.w + e.w);
            sC[kk][dd] = a;
        }
    }
    __syncthreads();

    // ---- A = bias @ R, B = bias @ C (128 active threads per half) ----
    {
        int whichB = tid >> 8;        // 0: A, 1: B
        int t = tid & 255;
        if (t < 128) {
            int a = t >> 2, dd = t & 3;
            float4 acc = make_float4(0.f, 0.f, 0.f, 0.f);
            const float4 (*src)[4] = whichB ? sC : sR;
            #pragma unroll
            for (int k = 0; k < 32; ++k) {
                float f = sb[a][k];
                float4 x = src[k][dd];
                acc.x = fmaf(f, x.x, acc.x);
                acc.y = fmaf(f, x.y, acc.y);
                acc.z = fmaf(f, x.z, acc.z);
                acc.w = fmaf(f, x.w, acc.w);
            }
            (whichB ? sB : sA)[a][dd] = acc;
        }
    }
    __syncthreads();

    // ---- write out: 4096 float4 over 512 threads = 8 iters ----
    {
        int jg = tid >> 2;            // 0..127
        float4* po = out4 + ((size_t)n * 1024) * 128 + h * 16 + q * 4 + d4;
        #pragma unroll
        for (int i = 0; i < 8; ++i) {
            int j = i * 128 + jg;
            int a = j >> 5, b = j & 31;
            float4 x = sA[a][d4];
            float4 y = sB[b][d4];
            x.x += y.x; x.y += y.y; x.z += y.z; x.w += y.w;
            po[(size_t)j * 128] = x;
        }
    }
}

extern "C" void kernel_launch(void* const* d_in, const int* in_sizes, int n_in,
                              void* d_out, int out_size) {
    const float* v = (const float*)d_in[0];
    const float* w = (const float*)d_in[1];
    if (n_in >= 2 && in_sizes[0] < in_sizes[1]) {
        const float* tmp = v; v = w; w = tmp;
    }

    fused_kernel<<<256, 512>>>((const float4*)v, w, (float4*)d_out);
}

// round 7
// speedup vs baseline: 1.1881x; 1.1881x over previous
#include <cuda_runtime.h>

// v: [8][1024][8][64] f32, w: [1][8][63] f32, out: [8][1024][8][64] f32
// Factorization (s=32, j = a*32+b, l = c*32+e):
//   out[n,j,h,d] = A[n,h,a,d] + B[n,h,b,d]
//   A = bias @ R,  B = bias @ C
//   R[c,d] = sum_e v[n, c*32+e, h, d],  C[e,d] = sum_c v[n, c*32+e, h, d]
//   bias[h,j,k] = w[h, (32 - k + j) mod 63]
//
// Single kernel. block = (n, h, d-half): grid=128 (FIXED: was 256), 256 thr.
// Thread (r,d4) accumulates BOTH R[r][d4] (32 contiguous rows) and C[r][d4]
// (32 stride-32 rows) in one interleaved register chain -> 2x MLP, misses
// to shared lines merge in L1tex. Two barriers total.

__global__ __launch_bounds__(256, 1)
void fused_kernel(const float4* __restrict__ v4,
                  const float*  __restrict__ w,
                  float4* __restrict__ out4) {
    int blk = blockIdx.x;          // 0..127
    int q = blk & 1;               // d-half: float4 cols [q*8, q*8+8)
    int h = (blk >> 1) & 7;
    int n = blk >> 4;              // 0..7
    int tid = threadIdx.x;

    __shared__ float4 sR[32][8], sC[32][8];
    __shared__ float4 sA[32][8], sB[32][8];
    __shared__ float  sb[32][33];

    int r  = tid >> 3;        // 0..31 : c for R-chain, e for C-chain, a for matvec
    int d4 = tid & 7;         // 0..7  : float4 column within the half

    const float4* base = v4 + ((size_t)n * 1024) * 128 + h * 16 + q * 8 + d4;

    // ---- Interleaved reduction: R[r] over rows r*32+i, C[r] over rows i*32+r ----
    {
        const float4* pR = base + (size_t)(r * 32) * 128;
        const float4* pC = base + (size_t)r * 128;
        float4 accR = make_float4(0.f, 0.f, 0.f, 0.f);
        float4 accC = make_float4(0.f, 0.f, 0.f, 0.f);
        #pragma unroll
        for (int i = 0; i < 32; ++i) {
            float4 x = pR[i * 128];
            float4 y = pC[i * 32 * 128];
            accR.x += x.x; accR.y += x.y; accR.z += x.z; accR.w += x.w;
            accC.x += y.x; accC.y += y.y; accC.z += y.z; accC.w += y.w;
        }
        sR[r][d4] = accR;
        sC[r][d4] = accC;
    }

    // ---- bias tile (4 entries/thread) ----
    for (int idx = tid; idx < 1024; idx += 256) {
        int j = idx >> 5, k = idx & 31;
        sb[j][k] = w[h * 63 + ((32 - k + j) % 63)];
    }
    __syncthreads();

    // ---- A[a][d4] = sum_k sb[a][k]*sR[k][d4]; B likewise from sC ----
    {
        float4 accA = make_float4(0.f, 0.f, 0.f, 0.f);
        float4 accB = make_float4(0.f, 0.f, 0.f, 0.f);
        #pragma unroll
        for (int k = 0; k < 32; ++k) {
            float f = sb[r][k];
            float4 x = sR[k][d4];
            float4 y = sC[k][d4];
            accA.x = fmaf(f, x.x, accA.x);
            accA.y = fmaf(f, x.y, accA.y);
            accA.z = fmaf(f, x.z, accA.z);
            accA.w = fmaf(f, x.w, accA.w);
            accB.x = fmaf(f, y.x, accB.x);
            accB.y = fmaf(f, y.y, accB.y);
            accB.z = fmaf(f, y.z, accB.z);
            accB.w = fmaf(f, y.w, accB.w);
        }
        sA[r][d4] = accA;
        sB[r][d4] = accB;
    }
    __syncthreads();

    // ---- write out: j = i*32 + r; out[n,j,h,half] = A[j>>5] + B[j&31] ----
    {
        float4* po = out4 + ((size_t)n * 1024) * 128 + h * 16 + q * 8 + d4;
        #pragma unroll
        for (int i = 0; i < 32; ++i) {
            int j = i * 32 + r;
            int a = j >> 5, b = j & 31;
            float4 x = sA[a][d4];
            float4 y = sB[b][d4];
            x.x += y.x; x.y += y.y; x.z += y.z; x.w += y.w;
            po[(size_t)j * 128] = x;
        }
    }
}

extern "C" void kernel_launch(void* const* d_in, const int* in_sizes, int n_in,
                              void* d_out, int out_size) {
    const float* v = (const float*)d_in[0];
    const float* w = (const float*)d_in[1];
    if (n_in >= 2 && in_sizes[0] < in_sizes[1]) {
        const float* tmp = v; v = w; w = tmp;
    }

    fused_kernel<<<128, 256>>>((const float4*)v, w, (float4*)d_out);
}